// round 15
// baseline (speedup 1.0000x reference)
#include <cuda_runtime.h>
#include <math.h>

#define NN 120000
#define CC 80
#define KK 300
#define MAXDET 100
#define BB 2
#define SCORE_THRES 0.99875f
#define NMS_THRES 0.5f
#define MIN_SIZE 0.001f
#define BBOX_CLIP 4.135166556742356f
#define IMG_W 1216.0f
#define IMG_H 800.0f
#define CAND_CAP 2048
#define SPEC 1024          // speculative prologue width
#define NW 5               // 5*64 = 320 bits >= KK=300
#define NWP 6              // padded mask row (48B, 16B-aligned)
#define TPB_MAIN 512

// Global scratch (zero-init at load; g_candCount reset at end of main_kernel)
__device__ __align__(16) unsigned long long g_candKeys[BB][CAND_CAP];
__device__ float4 g_candBox[BB][CAND_CAP];
__device__ int g_candCount[BB];

// -------- decode one anchor (matches reference exactly) --------
__device__ __forceinline__ float4 decode_box(const float* __restrict__ bp,
                                             const float* __restrict__ anc,
                                             int b, int n, bool* big) {
    float4 d = *(const float4*)(bp + ((size_t)b * NN + n) * 4);
    float4 a = *(const float4*)(anc + (size_t)n * 4);
    float wa = a.z - a.x;
    float ha = a.w - a.y;
    float cxa = a.x + 0.5f * wa;
    float cya = a.y + 0.5f * ha;
    float dw = fminf(d.z, BBOX_CLIP);
    float dh = fminf(d.w, BBOX_CLIP);
    float cx = d.x * wa + cxa;
    float cy = d.y * ha + cya;
    float w = expf(dw) * wa;
    float h = expf(dh) * ha;
    float x1 = fminf(fmaxf(cx - 0.5f * w, 0.0f), IMG_W);
    float y1 = fminf(fmaxf(cy - 0.5f * h, 0.0f), IMG_H);
    float x2 = fminf(fmaxf(cx + 0.5f * w, 0.0f), IMG_W);
    float y2 = fminf(fmaxf(cy + 0.5f * h, 0.0f), IMG_H);
    if (big) *big = (x2 - x1 >= MIN_SIZE) && (y2 - y1 >= MIN_SIZE);
    return make_float4(x1, y1, x2, y2);
}

__device__ __forceinline__ bool iou_gt(float4 bi, float ai, float4 bj, float aj) {
    float lx = fmaxf(bi.x, bj.x);
    float ly = fmaxf(bi.y, bj.y);
    float rx = fminf(bi.z, bj.z);
    float ry = fminf(bi.w, bj.w);
    float iw = fmaxf(rx - lx, 0.0f);
    float ih = fmaxf(ry - ly, 0.0f);
    float inter = iw * ih;
    return inter > NMS_THRES * (ai + aj - inter + 1e-9f);
}

// -------- fused init + class-0 candidate gather (whole chip) --------
__global__ void gather_init_kernel(const float* __restrict__ bp,
                                   const float* __restrict__ cp,
                                   const float* __restrict__ anc,
                                   float* __restrict__ out) {
    const int total5 = BB * CC * KK * 5;   // 240000
    const int totalL = BB * CC * KK;       // 48000
    int stride = gridDim.x * blockDim.x;
    int gid = blockIdx.x * blockDim.x + threadIdx.x;

    for (int t = gid; t < total5; t += stride) out[t] = 0.0f;
    for (int t = gid; t < totalL; t += stride) {
        int c = (t % (CC * KK)) / KK;
        out[total5 + t] = (float)c;
        out[total5 + totalL + t] = 0.0f;
    }

    for (int t = gid; t < BB * NN; t += stride) {
        int b = t / NN;
        int n = t - b * NN;
        float sc = __ldg(cp + (size_t)t * CC);   // class-0 score
        if (sc > SCORE_THRES) {
            bool big;
            float4 bx = decode_box(bp, anc, b, n, &big);
            if (big) {
                int pos = atomicAdd(&g_candCount[b], 1);
                if (pos < CAND_CAP) {
                    unsigned long long key =
                        ((unsigned long long)__float_as_uint(sc) << 32) |
                        (unsigned long long)(0xFFFFFFFFu - (unsigned)n);
                    g_candKeys[b][pos] = key;
                    g_candBox[b][pos] = bx;
                }
            }
        }
    }
}

// -------- per-image: sort / ballot NMS mask / greedy / class chain --------
__global__ void __launch_bounds__(TPB_MAIN) main_kernel(const float* __restrict__ cp,
                                                        float* __restrict__ out) {
    const int b = blockIdx.x;
    const int tid = threadIdx.x;
    const int bd = TPB_MAIN;
    const int lane = tid & 31;
    const int warpId = tid >> 5;
    const int numWarps = bd >> 5;    // 16

    __shared__ __align__(16) unsigned long long s_keys[CAND_CAP];
    __shared__ __align__(16) unsigned long long s_mask[KK][NWP];
    __shared__ unsigned long long s_nz[NW];
    __shared__ unsigned long long s_keepw[NW];
    __shared__ int s_wpref[NW];
    __shared__ float4 s_box[KK];
    __shared__ float s_sc[KK];
    __shared__ int s_aidx[KK];
    __shared__ int s_vidx[MAXDET];
    __shared__ float4 s_vbox[MAXDET];
    __shared__ int s_cnt;
    __shared__ int s_vcnt;

    float* out5 = out;                                               // [B][C*K][5]
    float* outK = out + (size_t)BB * CC * KK * 5 + (size_t)BB * CC * KK;

    // ---- prologue: count + speculative keys (one concurrent round trip) ----
    int m = g_candCount[b];
    unsigned long long k0 = g_candKeys[b][tid];
    unsigned long long k1 = g_candKeys[b][tid + 512];
    if (m > CAND_CAP) m = CAND_CAP;
    s_keys[tid]       = (tid < m)       ? k0 : 0ull;
    s_keys[tid + 512] = (tid + 512 < m) ? k1 : 0ull;
    if (m > SPEC) {     // rare path
        for (int i = tid + SPEC; i < CAND_CAP; i += bd)
            s_keys[i] = (i < m) ? g_candKeys[b][i] : 0ull;
    }
    if (tid < NW) s_nz[tid] = 0ull;
    if (tid == 32) s_cnt = 0;
    __syncthreads();

    // ---- rank sort (score desc, idx asc); box load overlaps rank scan ----
    const ulonglong2* k2 = (const ulonglong2*)s_keys;
    int mPairs = (m + 1) >> 1;
    for (int i = tid; i < m; i += bd) {
        float4 bx = g_candBox[b][i];       // issue early; latency hidden by scan
        unsigned long long ki = s_keys[i];
        int rank = 0;
        for (int j = 0; j < mPairs; j++) {
            ulonglong2 kk = k2[j];
            rank += (kk.x > ki) + (kk.y > ki);
        }
        if (rank < KK) {
            s_sc[rank] = __uint_as_float((unsigned)(ki >> 32));
            s_aidx[rank] = (int)(0xFFFFFFFFu - (unsigned)(ki & 0xFFFFFFFFull));
            s_box[rank] = bx;
        }
    }
    int nTop = (m < KK) ? m : KK;
    __syncthreads();

    for (int c = 0;; c++) {
        if (nTop > 0) {
            // ---- mask build: words outer (box regs hoisted), rows inner ----
            int nwA = (nTop + 63) >> 6;
            for (int w = 0; w < nwA; w++) {
                int j0 = (w << 6) + lane;
                int j1 = j0 + 32;
                bool v0 = j0 < nTop, v1 = j1 < nTop;
                float4 bj0, bj1;
                float aj0 = 0.f, aj1 = 0.f;
                if (v0) { bj0 = s_box[j0]; aj0 = (bj0.z - bj0.x) * (bj0.w - bj0.y); }
                if (v1) { bj1 = s_box[j1]; aj1 = (bj1.z - bj1.x) * (bj1.w - bj1.y); }
                for (int i = warpId; i < nTop; i += numWarps) {
                    float4 bi = s_box[i];                 // broadcast LDS
                    float ai = (bi.z - bi.x) * (bi.w - bi.y);
                    bool o0 = v0 && (j0 > i) && iou_gt(bi, ai, bj0, aj0);
                    bool o1 = v1 && (j1 > i) && iou_gt(bi, ai, bj1, aj1);
                    unsigned lo = __ballot_sync(0xFFFFFFFFu, o0);
                    unsigned hi = __ballot_sync(0xFFFFFFFFu, o1);
                    if (lane == 0) {
                        unsigned long long bits =
                            ((unsigned long long)hi << 32) | (unsigned long long)lo;
                        s_mask[i][w] = bits;
                        if (bits) atomicOr(&s_nz[i >> 6], 1ull << (i & 63));
                    }
                }
            }
            __syncthreads();

            // ---- sequential greedy over kept SUPPRESSOR rows (thread 0) ----
            if (tid == 0) {
                unsigned long long kw[NW], nz[NW];
                #pragma unroll
                for (int w = 0; w < NW; w++) {
                    int nn = nTop - w * 64;
                    kw[w] = (nn <= 0) ? 0ull : ((nn >= 64) ? ~0ull : ((1ull << nn) - 1ull));
                    nz[w] = s_nz[w];
                    s_nz[w] = 0ull;
                }
                #pragma unroll
                for (int w = 0; w < NW; w++) {
                    unsigned long long live = kw[w] & nz[w];
                    while (live) {
                        int bpos = __ffsll((long long)live) - 1;
                        int i = w * 64 + bpos;
                        const ulonglong2* mrow = (const ulonglong2*)s_mask[i];
                        ulonglong2 m01 = mrow[0];
                        ulonglong2 m23 = mrow[1];
                        ulonglong2 m45 = mrow[2];
                        kw[0] &= ~m01.x; kw[1] &= ~m01.y;
                        kw[2] &= ~m23.x; kw[3] &= ~m23.y;
                        kw[4] &= ~m45.x;
                        live = (bpos == 63) ? 0ull
                             : (kw[w] & nz[w] & (~0ull << (bpos + 1)));
                    }
                }
                // MAX_DET cap
                int cnt = 0;
                #pragma unroll
                for (int w = 0; w < NW; w++) {
                    unsigned long long v = kw[w];
                    int pc = __popcll(v);
                    if (cnt >= MAXDET) v = 0ull;
                    else if (cnt + pc > MAXDET) {
                        int allowed = MAXDET - cnt;
                        unsigned long long r = v;
                        for (int q = 0; q < allowed; q++) r &= r - 1;
                        v &= ~r;
                        cnt = MAXDET;
                    } else cnt += pc;
                    s_keepw[w] = v;
                }
                int p = 0;
                #pragma unroll
                for (int w = 0; w < NW; w++) { s_wpref[w] = p; p += __popcll(s_keepw[w]); }
                s_vcnt = p;
                s_cnt = 0;
            }
            __syncthreads();

            // ---- write outputs + rebuild valid set + NEXT-class keys (fused) ----
            for (int r = tid; r < nTop; r += bd) {
                int w = r >> 6, bpos = r & 63;
                unsigned long long v = s_keepw[w];
                if ((v >> bpos) & 1ull) {
                    size_t row = ((size_t)b * CC + c) * KK + r;
                    float4 bx = s_box[r];
                    out5[row * 5 + 0] = bx.x;
                    out5[row * 5 + 1] = bx.y;
                    out5[row * 5 + 2] = bx.z;
                    out5[row * 5 + 3] = bx.w;
                    out5[row * 5 + 4] = s_sc[r];
                    outK[row] = 1.0f;
                    int p = s_wpref[w] + __popcll(v & ((1ull << bpos) - 1ull));
                    int aidx = s_aidx[r];
                    s_vidx[p] = aidx;
                    s_vbox[p] = bx;
                    if (c < CC - 1) {
                        float sc = cp[((size_t)b * NN + aidx) * CC + (c + 1)];
                        unsigned long long key = 0ull;
                        if (sc > SCORE_THRES) {
                            key = ((unsigned long long)__float_as_uint(sc) << 32) |
                                  (unsigned long long)(0xFFFFFFFFu - (unsigned)aidx);
                            atomicAdd(&s_cnt, 1);
                        }
                        s_keys[p] = key;
                    }
                }
            }
            __syncthreads();
        } else {
            if (tid == 0) { s_vcnt = 0; s_cnt = 0; }
            __syncthreads();
        }

        if (c == CC - 1) break;
        int vm = s_vcnt;
        if (vm == 0) break;
        int nc = s_cnt;
        if (nc == 0) break;

        // ---- rank sort next-class candidates (vm <= 100) ----
        for (int i = tid; i < vm; i += bd) {
            unsigned long long ki = s_keys[i];
            if (ki == 0ull) continue;
            int rank = 0;
            for (int j = 0; j < vm; j++) rank += (s_keys[j] > ki) ? 1 : 0;
            s_sc[rank] = __uint_as_float((unsigned)(ki >> 32));
            s_aidx[rank] = s_vidx[i];
            s_box[rank] = s_vbox[i];
        }
        __syncthreads();
        nTop = nc;
    }

    // reset counter for next graph replay (stream-ordered wrt next launch)
    __syncthreads();
    if (tid == 0) g_candCount[b] = 0;
}

extern "C" void kernel_launch(void* const* d_in, const int* in_sizes, int n_in,
                              void* d_out, int out_size) {
    const float* bp  = (const float*)d_in[0];  // box_preds  [B,N,4]
    const float* cp  = (const float*)d_in[1];  // cls_preds  [B,N,C]
    const float* anc = (const float*)d_in[2];  // anchors    [N,4]
    float* out = (float*)d_out;

    gather_init_kernel<<<(BB * NN + 255) / 256, 256>>>(bp, cp, anc, out);
    main_kernel<<<BB, TPB_MAIN>>>(cp, out);
}